// round 9
// baseline (speedup 1.0000x reference)
#include <cuda_runtime.h>
#include <cuda_fp16.h>
#include <cstdint>
#include <cstddef>

#define NTHREADS 512

#define FMA_F32X2(d, a, b, c) \
    asm("fma.rn.f32x2 %0, %1, %2, %3;" : "=l"(d) : "l"(a), "l"(b), "l"(c))
#define PACK2(d, lo, hi) \
    asm("mov.b64 %0, {%1, %2};" : "=l"(d) : "f"(lo), "f"(hi))
#define UNPACK2(lo, hi, s) \
    asm("mov.b64 {%0, %1}, %2;" : "=f"(lo), "=f"(hi) : "l"(s))

// ---------------------------------------------------------------------------
// 512 threads/CTA, 8-CTA cluster per batch. NO register-resident weights (the
// R6 spill lesson). All weights in SMEM with conflict-free padded layouts.
// Quad = (word>>2) mod 8; LDS.128 phases are 8-lane groups; every hot load
// pattern below has bijective (or broadcast) quads per phase:
//  - P fp32 stride 68, scalar LDS: bank = 4j+q+4i, bijective per warp.
//  - W1hH half2: row 160, chunk 20 (32 h-cols/chunk): quad = 5s+i (5 coprime 8).
//  - WhhH half2: row 144, chunk 36 (64 cols/chunk): quad = 4r+p+4c2+i.
//  - GxH  half2: row  80, chunk 20 (32 j/chunk):   quad = 4r+5p+i.
//  - Hc fp32 padded chunks of 36: quad = s+i (Q) / 2p+c2+2i broadcast (gates).
//  - PEt fp32 [j][12]: float4 quad = 3j+i (3 coprime 8).
// ---------------------------------------------------------------------------
struct __align__(16) Smem {
    float   P[128 * 68];      // 34816 B  [j][kk] x-part of energy L1 (+b1)
    __half2 GxH[128 * 80];    // 40960 B  [gate row][j] Wih_row . x_j
    __half2 W1hH[64 * 160];   // 40960 B  [kk][h] W1 h-part (fp32 staging in prologue)
    __half2 WhhH[128 * 144];  // 73728 B  [gate row][h]
    float   Hc[2 * 288];      // 2304 B   double-buffered hidden, padded chunks
    float   PEt[128 * 12];    // 6144 B   [j][src_rank] partial energies
    float   Qv[64];
    float   W2s[64];
    float   G[128];
    float   Bias[128];
    __half2 WgtH[80];         // softmax weights, chunked like GxH columns
    float   Hnew[32];
    float   pad2[4];
};
// total = 200,912 B  (< 232,448 max dynamic smem)

__device__ __forceinline__ uint32_t s2u(const void* p) {
    uint32_t a;
    asm("{ .reg .u64 t; cvta.to.shared.u64 t, %1; cvt.u32.u64 %0, t; }"
        : "=r"(a) : "l"(p));
    return a;
}
__device__ __forceinline__ uint32_t mapa_rank(uint32_t addr, uint32_t rank) {
    uint32_t r;
    asm("mapa.shared::cluster.u32 %0, %1, %2;" : "=r"(r) : "r"(addr), "r"(rank));
    return r;
}
__device__ __forceinline__ void st_remote(uint32_t addr, float v) {
    asm volatile("st.shared::cluster.f32 [%0], %1;" :: "r"(addr), "f"(v) : "memory");
}
__device__ __forceinline__ void cluster_arrive() {
    asm volatile("barrier.cluster.arrive.aligned;" ::: "memory");
}
__device__ __forceinline__ void cluster_wait() {
    asm volatile("barrier.cluster.wait.aligned;" ::: "memory");
}
__device__ __forceinline__ float tanh_fast(float x) {   // MUFU, inner hdn only
    float y; asm("tanh.approx.f32 %0, %1;" : "=f"(y) : "f"(x)); return y;
}
__device__ __forceinline__ float tanh_acc(float x) {    // ~1e-6 err
    float e = __expf(2.f * x);
    return 1.f - __fdividef(2.f, e + 1.f);
}
__device__ __forceinline__ float sigm(float x) { return 1.f / (1.f + __expf(-x)); }

__global__ void __cluster_dims__(8, 1, 1) __launch_bounds__(NTHREADS, 1)
lstm_attn_kernel(const float* __restrict__ gx, const int* __restrict__ gseq,
                 const float* __restrict__ gW1, const float* __restrict__ gb1,
                 const float* __restrict__ gW2, const float* __restrict__ gb2,
                 const float* __restrict__ gWih, const float* __restrict__ gWhh,
                 const float* __restrict__ gbih, const float* __restrict__ gbhh,
                 float* __restrict__ out)
{
    extern __shared__ char smraw[];
    Smem& sm = *reinterpret_cast<Smem*>(smraw);
    const int tid = (int)threadIdx.x;
    const int b   = (int)blockIdx.x >> 3;   // batch = cluster id
    const int c   = (int)blockIdx.x & 7;    // rank within cluster
    const int len = gseq[b];
    const int lane = tid & 31;

    float* outO = out;                      // outputs  [8][128][256]
    float* outL = out + 262144;             // seq_lengths [8]
    float* outH = out + 262152;             // hidden   [1][8][256]
    float* outA = out + 264200;             // attn     [8][128][128]

    // ---------------- prologue ----------------
    for (int i = tid; i < 2 * 288; i += NTHREADS) sm.Hc[i] = 0.f;

    {   // zero padded output rows (d_out is poisoned)
        const int padT = 128 - len;
        for (int idx = (c << 9) + tid; idx < padT * 256; idx += 4096)
            outO[(size_t)b * 32768 + (size_t)len * 256 + idx] = 0.f;
        for (int idx = (c << 9) + tid; idx < padT * 128; idx += 4096)
            outA[(size_t)b * 16384 + (size_t)len * 128 + idx] = 0.f;
        if (c == 0 && tid == 0) outL[b] = (float)len;
    }

    // Unified prologue GEMM: 192 W-rows (64 -> P slice, 128 -> GxH) x 128 j.
    // thread = (j = tid>>2, qq = tid&3 e-quarter); x quarter in f32x2 regs.
    {
        const int jq = tid >> 2;
        const int qq = tid & 3;
        float* wst = reinterpret_cast<float*>(sm.W1hH);  // 16 x 272 fp32 staging

        unsigned long long xp[32];                       // x[j, 64qq..64qq+64)
        {
            const float* xrow = gx + (size_t)b * 32768 + (size_t)jq * 256 + qq * 64;
            #pragma unroll
            for (int i = 0; i < 16; ++i) {
                ulonglong2 v = *reinterpret_cast<const ulonglong2*>(xrow + 4 * i);
                xp[2 * i] = v.x; xp[2 * i + 1] = v.y;
            }
        }

        for (int pass = 0; pass < 12; ++pass) {
            __syncthreads();                 // prior-pass wst reads complete
            for (int i = tid; i < 16 * 256; i += NTHREADS) {
                int r = i >> 8, e = i & 255;
                int row = pass * 16 + r;
                float v;
                if (row < 64) {
                    v = gW1[(size_t)(c * 64 + row) * 512 + e];
                } else {
                    int idx = row - 64, g = idx >> 5, u = idx & 31;
                    v = gWih[(size_t)(g * 256 + c * 32 + u) * 256 + e];
                }
                wst[r * 272 + (e >> 6) * 68 + (e & 63)] = v;
            }
            __syncthreads();

            #pragma unroll 2
            for (int r = 0; r < 16; ++r) {
                const ulonglong2* wr =
                    reinterpret_cast<const ulonglong2*>(wst + r * 272 + qq * 68);
                unsigned long long acc0, acc1;
                PACK2(acc0, 0.f, 0.f);
                PACK2(acc1, 0.f, 0.f);
                #pragma unroll
                for (int i = 0; i < 16; ++i) {
                    ulonglong2 w = wr[i];
                    FMA_F32X2(acc0, xp[2 * i],     w.x, acc0);
                    FMA_F32X2(acc1, xp[2 * i + 1], w.y, acc1);
                }
                float l0, h0, l1, h1;
                UNPACK2(l0, h0, acc0);
                UNPACK2(l1, h1, acc1);
                float s = (l0 + h0) + (l1 + h1);
                s += __shfl_xor_sync(0xffffffffu, s, 1);
                s += __shfl_xor_sync(0xffffffffu, s, 2);
                if (qq == 0) {
                    int row = pass * 16 + r;
                    if (row < 64) {
                        sm.P[jq * 68 + row] = s + gb1[c * 64 + row];
                    } else {
                        int idx = row - 64;
                        reinterpret_cast<__half*>(sm.GxH)
                            [idx * 160 + (jq >> 5) * 40 + (jq & 31)] = __float2half_rn(s);
                    }
                }
            }
        }
        __syncthreads();                     // last-pass wst reads complete
    }

    // W1h fp16 (overwrites its own staging area)
    for (int i = tid; i < 64 * 128; i += NTHREADS) {
        int kk = i >> 7, m = i & 127;
        float2 v = *reinterpret_cast<const float2*>(
            gW1 + (size_t)(c * 64 + kk) * 512 + 256 + 2 * m);
        int hh = 2 * m;
        sm.W1hH[kk * 160 + (hh >> 5) * 20 + ((hh & 31) >> 1)] = __floats2half2_rn(v.x, v.y);
    }
    // Whh fp16 slice: our rows gate g, unit c*32+u
    for (int i = tid; i < 128 * 128; i += NTHREADS) {
        int r = i >> 7, m = i & 127;
        int grow = (r >> 5) * 256 + c * 32 + (r & 31);
        float2 v = *reinterpret_cast<const float2*>(gWhh + (size_t)grow * 256 + 2 * m);
        int col = 2 * m;
        sm.WhhH[r * 144 + (col >> 6) * 36 + ((col & 63) >> 1)] = __floats2half2_rn(v.x, v.y);
    }
    if (tid < 64) sm.W2s[tid] = gW2[c * 64 + tid];
    if (tid < 128) {
        int g = tid >> 5, uu = tid & 31;
        sm.Bias[tid] = gbih[g * 256 + c * 32 + uu] + gbhh[g * 256 + c * 32 + uu];
    }
    __syncthreads();
    cluster_arrive(); cluster_wait();

    // hoisted remote base addresses (mapa once, not per store)
    uint32_t peR[8], hcR[8];
    {
        uint32_t peA = s2u(sm.PEt), hcA = s2u(sm.Hc);
        #pragma unroll
        for (int rr = 0; rr < 8; ++rr) {
            peR[rr] = mapa_rank(peA, rr);
            hcR[rr] = mapa_rank(hcA, rr);
        }
    }

    const float b2v = gb2[0];
    float creg = 0.f, hlast = 0.f;          // per-unit state (threads 0..31)
    const int gr = tid >> 2, gp = tid & 3;  // gate row / quarter mapping

    // ---------------- time loop (only observable steps) ----------------
    for (int t = 0; t < len; ++t) {
        const float* Hcur = sm.Hc + (t & 1) * 288;

        // ---- Q[kk] = h . W1h[kk,:]   (kk = tid>>3, s = tid&7 h-chunk) ----
        {
            const int kk = tid >> 3, s = tid & 7;
            const float4* wr = reinterpret_cast<const float4*>(sm.W1hH + kk * 160 + s * 20);
            const float4* hr = reinterpret_cast<const float4*>(Hcur + s * 36);
            float a0 = 0.f, a1 = 0.f;
            #pragma unroll
            for (int i2 = 0; i2 < 4; ++i2) {
                float4 wv = wr[i2];                       // 4 half2 = 8 cols
                float4 hv0 = hr[2 * i2], hv1 = hr[2 * i2 + 1];
                float2 w0 = __half22float2(*reinterpret_cast<const __half2*>(&wv.x));
                float2 w1 = __half22float2(*reinterpret_cast<const __half2*>(&wv.y));
                float2 w2 = __half22float2(*reinterpret_cast<const __half2*>(&wv.z));
                float2 w3 = __half22float2(*reinterpret_cast<const __half2*>(&wv.w));
                a0 = fmaf(w0.x, hv0.x, a0); a1 = fmaf(w0.y, hv0.y, a1);
                a0 = fmaf(w1.x, hv0.z, a0); a1 = fmaf(w1.y, hv0.w, a1);
                a0 = fmaf(w2.x, hv1.x, a0); a1 = fmaf(w2.y, hv1.y, a1);
                a0 = fmaf(w3.x, hv1.z, a0); a1 = fmaf(w3.y, hv1.w, a1);
            }
            float acc = a0 + a1;
            acc += __shfl_xor_sync(0xffffffffu, acc, 1);
            acc += __shfl_xor_sync(0xffffffffu, acc, 2);
            acc += __shfl_xor_sync(0xffffffffu, acc, 4);
            if (s == 0) sm.Qv[kk] = acc;
        }
        __syncthreads();

        // ---- partial energies: pe[j] = sum_kk tanh(P+Q)*W2 (j=tid>>2,q=tid&3) ----
        {
            const int j = tid >> 2, q = tid & 3;
            float acc = 0.f;
            #pragma unroll
            for (int i = 0; i < 16; ++i) {
                int kk = q + 4 * i;
                float v = sm.P[j * 68 + kk] + sm.Qv[kk];
                acc = fmaf(tanh_fast(v), sm.W2s[kk], acc);
            }
            acc += __shfl_xor_sync(0xffffffffu, acc, 1);
            acc += __shfl_xor_sync(0xffffffffu, acc, 2);
            if (q == 0) {
                uint32_t off = (uint32_t)((j * 12 + c) * 4);
                #pragma unroll
                for (int rr = 0; rr < 8; ++rr) st_remote(peR[rr] + off, acc);
            }
        }
        cluster_arrive();   // B1 arrive: PE in flight

        // ---- hidden behind B1: Whh quarter of the gates (indep. of PE) ----
        float a_hh;
        {
            float a0 = 0.f, a1 = 0.f, a2 = 0.f, a3 = 0.f;
            const __half2* wr = sm.WhhH + gr * 144 + gp * 36;
            #pragma unroll
            for (int c2 = 0; c2 < 2; ++c2) {
                const float4* hrc = reinterpret_cast<const float4*>(Hcur + gp * 72 + c2 * 36);
                const float4* wrc = reinterpret_cast<const float4*>(wr + c2 * 16);
                #pragma unroll
                for (int i2 = 0; i2 < 4; ++i2) {
                    float4 wv = wrc[i2];
                    float4 h0 = hrc[2 * i2], h1 = hrc[2 * i2 + 1];
                    float2 w0 = __half22float2(*reinterpret_cast<const __half2*>(&wv.x));
                    float2 w1 = __half22float2(*reinterpret_cast<const __half2*>(&wv.y));
                    float2 w2 = __half22float2(*reinterpret_cast<const __half2*>(&wv.z));
                    float2 w3 = __half22float2(*reinterpret_cast<const __half2*>(&wv.w));
                    a0 = fmaf(w0.x, h0.x, a0); a1 = fmaf(w0.y, h0.y, a1);
                    a2 = fmaf(w1.x, h0.z, a2); a3 = fmaf(w1.y, h0.w, a3);
                    a0 = fmaf(w2.x, h1.x, a0); a1 = fmaf(w2.y, h1.y, a1);
                    a2 = fmaf(w3.x, h1.z, a2); a3 = fmaf(w3.y, h1.w, a3);
                }
            }
            a_hh = (a0 + a1) + (a2 + a3);
        }
        cluster_wait();     // B1 wait: PE ready everywhere

        // ---- warp-local softmax (each warp computes all 128 j's, no syncs,
        //      no max-subtraction: energies are tanh-bounded in (-1,1)) ----
        {
            float w[4];
            float ssum = 0.f;
            #pragma unroll
            for (int qd = 0; qd < 4; ++qd) {
                const int j = lane + 32 * qd;
                const float4* pej = reinterpret_cast<const float4*>(sm.PEt + j * 12);
                float4 u0 = pej[0], u1 = pej[1];
                float s = ((u0.x + u0.y) + (u0.z + u0.w)) +
                          ((u1.x + u1.y) + (u1.z + u1.w));
                float e = (j < len) ? tanh_acc(s + b2v) : -1e30f;
                w[qd] = __expf(e);
                ssum += w[qd];
            }
            #pragma unroll
            for (int o = 16; o; o >>= 1) ssum += __shfl_xor_sync(0xffffffffu, ssum, o);
            const float inv = __fdividef(1.f, ssum);
            #pragma unroll
            for (int qd = 0; qd < 4; ++qd) {
                w[qd] *= inv;
                float hi = __shfl_down_sync(0xffffffffu, w[qd], 1);
                if (!(lane & 1))
                    sm.WgtH[qd * 20 + (lane >> 1)] = __floats2half2_rn(w[qd], hi);
            }
            if (c == 0 && tid < 32) {
                float* row = outA + (size_t)(b * 128 + t) * 128;
                #pragma unroll
                for (int qd = 0; qd < 4; ++qd) row[lane + 32 * qd] = w[qd];
            }
        }
        __syncwarp();

        // ---- gates: a_hh + sum_j w_j * Gx[row][j]  (quarter gp of j) ----
        {
            float a0 = a_hh, a1 = 0.f;
            const float4* gx4 = reinterpret_cast<const float4*>(sm.GxH + gr * 80 + gp * 20);
            const float4* wv4 = reinterpret_cast<const float4*>(sm.WgtH + gp * 20);
            #pragma unroll
            for (int i2 = 0; i2 < 4; ++i2) {
                float4 g4 = gx4[i2];
                float4 w4 = wv4[i2];
                float2 g0 = __half22float2(*reinterpret_cast<const __half2*>(&g4.x));
                float2 g1 = __half22float2(*reinterpret_cast<const __half2*>(&g4.y));
                float2 g2 = __half22float2(*reinterpret_cast<const __half2*>(&g4.z));
                float2 g3 = __half22float2(*reinterpret_cast<const __half2*>(&g4.w));
                float2 q0 = __half22float2(*reinterpret_cast<const __half2*>(&w4.x));
                float2 q1 = __half22float2(*reinterpret_cast<const __half2*>(&w4.y));
                float2 q2 = __half22float2(*reinterpret_cast<const __half2*>(&w4.z));
                float2 q3 = __half22float2(*reinterpret_cast<const __half2*>(&w4.w));
                a0 = fmaf(q0.x, g0.x, a0); a1 = fmaf(q0.y, g0.y, a1);
                a0 = fmaf(q1.x, g1.x, a0); a1 = fmaf(q1.y, g1.y, a1);
                a0 = fmaf(q2.x, g2.x, a0); a1 = fmaf(q2.y, g2.y, a1);
                a0 = fmaf(q3.x, g3.x, a0); a1 = fmaf(q3.y, g3.y, a1);
            }
            float acc = a0 + a1;
            acc += __shfl_xor_sync(0xffffffffu, acc, 1);
            acc += __shfl_xor_sync(0xffffffffu, acc, 2);
            if (gp == 0) sm.G[gr] = acc + sm.Bias[gr];
        }
        __syncthreads();

        // ---- state update (32 units per CTA) ----
        if (tid < 32) {
            float gi = sm.G[tid],      gf = sm.G[32 + tid];
            float gg = sm.G[64 + tid], go = sm.G[96 + tid];
            creg = sigm(gf) * creg + sigm(gi) * tanh_acc(gg);
            float hn = sigm(go) * tanh_acc(creg);
            if (t == len - 1) hlast = hn;
            outO[(size_t)(b * 128 + t) * 256 + (c * 32 + tid)] = hn;
            sm.Hnew[tid] = hn;
        }
        __syncthreads();

        // ---- all-gather h into the NEXT Hc buffer (padded chunk c) ----
        if (tid < 256) {
            const int rk = tid >> 5, uu = tid & 31;
            uint32_t off = (uint32_t)(((((t + 1) & 1) * 288) + c * 36 + uu) * 4);
            st_remote(hcR[rk] + off, sm.Hnew[uu]);
        }
        cluster_arrive();   // B3
        cluster_wait();     // h ready for step t+1
    }

    if (tid < 32)
        outH[(size_t)b * 256 + c * 32 + tid] = hlast;
}

extern "C" void kernel_launch(void* const* d_in, const int* in_sizes, int n_in,
                              void* d_out, int out_size) {
    (void)in_sizes; (void)n_in; (void)out_size;
    const float* x    = (const float*)d_in[0];
    const int*   seq  = (const int*)d_in[1];
    const float* W1   = (const float*)d_in[2];
    const float* b1   = (const float*)d_in[3];
    const float* W2   = (const float*)d_in[4];
    const float* b2   = (const float*)d_in[5];
    const float* Wih  = (const float*)d_in[6];
    const float* Whh  = (const float*)d_in[7];
    const float* bih  = (const float*)d_in[8];
    const float* bhh  = (const float*)d_in[9];
    float* out = (float*)d_out;

    cudaFuncSetAttribute(lstm_attn_kernel,
                         cudaFuncAttributeMaxDynamicSharedMemorySize,
                         (int)sizeof(Smem));
    lstm_attn_kernel<<<64, NTHREADS, sizeof(Smem)>>>(
        x, seq, W1, b1, W2, b2, Wih, Whh, bih, bhh, out);
}